// round 15
// baseline (speedup 1.0000x reference)
#include <cuda_runtime.h>
#include <math.h>
#include <float.h>

#define T2       2
#define BATCH    256
#define NSAMP    80000
#define NPERSEG  100
#define NFREQ    51
#define NSEG     800
#define COLS     (BATCH * NFREQ)         // 13056 = 51*256
#define NSPB     2
#define NORMBLKS (NSEG / NSPB)           // 400
#define IPB      42                      // instances per psd block (14 warps x 3)
#define PSDTHR   448
#define XS_W     108                     // padded xs row stride (words); 108%32=12
#define TOT_T    (NSEG * BATCH)          // 204800 per tensor
#define PSDBLKX  ((TOT_T + IPB - 1) / IPB)  // 4877

#define TWO_PI 6.28318530717958647692f

__device__ constexpr float C10[10] = {
     1.0f,  0.80901699437494745f,  0.30901699437494745f, -0.30901699437494745f,
    -0.80901699437494745f, -1.0f, -0.80901699437494745f, -0.30901699437494745f,
     0.30901699437494745f,  0.80901699437494745f };
__device__ constexpr float S10[10] = {
     0.0f,  0.58778525229247314f,  0.95105651629515353f,  0.95105651629515353f,
     0.58778525229247314f,  0.0f, -0.58778525229247314f, -0.95105651629515353f,
    -0.95105651629515353f, -0.58778525229247314f };

// Scratch: signed-clamp-log PSD (unnormalized). 83.6 MB.
__device__ float  g_L[T2][NSEG][COLS];
__device__ float  g_colsum[T2][COLS];
__device__ double g_saTot[T2];
__device__ double g_acc[2];      // [0]=sum SF*SR, [1]=sum SF*SF
__device__ unsigned int g_done;  // dot-block completion counter

__device__ __forceinline__ float sclog(float p) {
    float lx = __logf(p);
    float s  = (lx > 0.0f) ? 1.0f : ((lx < 0.0f) ? -1.0f : 0.0f);
    return s * fmaxf(fabsf(lx), 1e-6f);
}

__device__ __forceinline__ float2 cmul(float2 a, float2 b) {
    return make_float2(fmaf(a.x, b.x, -a.y * b.y), fmaf(a.x, b.y, a.y * b.x));
}

// ---------------------------------------------------------------------------
// Kernel A: Welch -> 10x10 CT rDFT(100), real/conjugate folded.
// Grid (PSDBLKX, 2); blockIdx.y = tensor. Warp = 3 instances x 10 lanes.
// Stage-2 twiddles from register recurrence. min-4-blocks forces regs <= 36.
// Table build via __sincosf (MUFU fast path).
__global__ __launch_bounds__(PSDTHR, 4) void psd_kernel(const float* __restrict__ fake,
                                                        const float* __restrict__ real_) {
    __shared__ __align__(16) float wnd[NPERSEG];
    __shared__ float2 tws[NPERSEG];          // e^{-2 pi i k/100}
    __shared__ __align__(16) float xs[IPB][XS_W];
    __shared__ float2 Ysh[IPB][10][6];
    __shared__ float  psd_s[IPB][NFREQ];

    const int tid = threadIdx.x;

    // Fold in accumulator zeroing (replaces zero_kernel).
    if (blockIdx.y == 0) {
        int gid = blockIdx.x * PSDTHR + tid;
        if (gid < T2 * COLS) ((float*)g_colsum)[gid] = 0.0f;
        if (blockIdx.x == 0) {
            if (tid < T2) g_saTot[tid] = 0.0;
            if (tid >= 2 && tid < 4) g_acc[tid - 2] = 0.0;
            if (tid == 4) g_done = 0u;
        }
    }

    if (tid < NPERSEG) {
        float s, c;
        __sincosf(TWO_PI * 0.01f * (float)tid, &s, &c);
        tws[tid] = make_float2(c, -s);
        wnd[tid] = 1.0f - c;                 // hann(periodic)*2
    }
    __syncthreads();

    const int t = blockIdx.y;
    const float* __restrict__ base = (t == 0) ? fake : real_;

    const int warp = tid >> 5, lane = tid & 31;
    const int base_inst = warp * 3;
    const int gbase = blockIdx.x * IPB + base_inst;   // per-tensor instance id

    // ---- stage 0: vectorized load + clamp + window into smem (float4) ----
    #pragma unroll
    for (int k = 0; k < 3; ++k) {
        int g = gbase + k;
        if (g >= TOT_T) break;
        int seg = g >> 8, b = g & 255;
        const float4* __restrict__ src4 =
            (const float4*)(base + (size_t)b * NSAMP + seg * NPERSEG);
        if (lane < 25) {
            float4 v = src4[lane];
            float4 w = ((const float4*)wnd)[lane];
            float4 o;
            o.x = fmaxf(v.x, 1e-6f) * w.x;
            o.y = fmaxf(v.y, 1e-6f) * w.y;
            o.z = fmaxf(v.z, 1e-6f) * w.z;
            o.w = fmaxf(v.w, 1e-6f) * w.w;
            ((float4*)xs[base_inst + k])[lane] = o;
        }
    }
    __syncwarp();

    const int  ik   = lane / 10;             // 0..2
    const int  role = lane - ik * 10;        // 0..9 (q in stage1, m in stage2)
    const int  inst = base_inst + ik;
    const bool act  = (lane < 30) && (gbase + ik < TOT_T);

    // ---- stage 1: Y[q][r] = sum_a x[10a+q] w10^{ra}, r=0..5, real-folded ----
    if (act) {
        float x[10];
        #pragma unroll
        for (int a = 0; a < 10; ++a) x[a] = xs[inst][a * 10 + role];
        float s1 = x[1] + x[9], d1 = x[1] - x[9];
        float s2 = x[2] + x[8], d2 = x[2] - x[8];
        float s3 = x[3] + x[7], d3 = x[3] - x[7];
        float s4 = x[4] + x[6], d4 = x[4] - x[6];
        float ex = x[0] + x[5], ox = x[0] - x[5];
        float sv[5] = {0.0f, s1, s2, s3, s4};
        float dv[5] = {0.0f, d1, d2, d3, d4};

        Ysh[inst][role][0] = make_float2(ex + s1 + s2 + s3 + s4, 0.0f);
        Ysh[inst][role][5] = make_float2(ox - s1 + s2 - s3 + s4, 0.0f);
        #pragma unroll
        for (int r = 1; r < 5; ++r) {
            float re = (r & 1) ? ox : ex;
            float im = 0.0f;
            #pragma unroll
            for (int a = 1; a < 5; ++a) {
                const int k = (r * a) % 10;
                re = fmaf(sv[a],  C10[k], re);
                im = fmaf(dv[a], -S10[k], im);
            }
            Ysh[inst][role][r] = make_float2(re, im);
        }
    }
    __syncwarp();

    // ---- stage 2: Z[q] = e1^q * Y~[q]; DFT-10 over j with q-folding -------
    if (act) {
        const int   m  = role;
        const int   c  = (m <= 5) ? m : 10 - m;
        const float cj = (m <= 5) ? 1.0f : -1.0f;

        const float2 e1 = tws[m];            // single LDS.64
        const float2 e2 = cmul(e1, e1);

        float Zr[10], Zi[10];
        {
            float2 y = Ysh[inst][0][c];
            Zr[0] = y.x;
            Zi[0] = y.y * cj;
        }
        {   // odd chain: q = 1,3,5,7,9 stepping by e2
            float2 e = e1;
            #pragma unroll
            for (int q = 1; q <= 9; q += 2) {
                float2 y = Ysh[inst][q][c];
                float  yi = y.y * cj;
                Zr[q] = fmaf(e.x, y.x, -e.y * yi);
                Zi[q] = fmaf(e.x, yi,   e.y * y.x);
                if (q < 9) e = cmul(e, e2);
            }
        }
        {   // even chain: q = 2,4,6,8 stepping by e2
            float2 e = e2;
            #pragma unroll
            for (int q = 2; q <= 8; q += 2) {
                float2 y = Ysh[inst][q][c];
                float  yi = y.y * cj;
                Zr[q] = fmaf(e.x, y.x, -e.y * yi);
                Zi[q] = fmaf(e.x, yi,   e.y * y.x);
                if (q < 8) e = cmul(e, e2);
            }
        }

        float P[5], Mr[5], Pi[5], Mi[5];
        #pragma unroll
        for (int q = 1; q < 5; ++q) {
            P [q] = Zr[q] + Zr[10 - q];
            Mr[q] = Zr[q] - Zr[10 - q];
            Pi[q] = Zi[q] + Zi[10 - q];
            Mi[q] = Zi[q] - Zi[10 - q];
        }
        const float er = Zr[0] + Zr[5], orr = Zr[0] - Zr[5];
        const float ei = Zi[0] + Zi[5], oi  = Zi[0] - Zi[5];

        float* outp = psd_s[inst];
        {
            float Xr = er + P[1] + P[2] + P[3] + P[4];
            float Xi = ei + Pi[1] + Pi[2] + Pi[3] + Pi[4];
            outp[m] = sclog(fmaf(Xr, Xr, Xi * Xi));
        }
        #pragma unroll
        for (int j = 1; j < 5; ++j) {
            float Xr = (j & 1) ? orr : er;
            float Xi = (j & 1) ? oi  : ei;
            #pragma unroll
            for (int q = 1; q < 5; ++q) {
                const int k = (j * q) % 10;
                Xr = fmaf(P [q],  C10[k], Xr);
                Xr = fmaf(Mi[q],  S10[k], Xr);
                Xi = fmaf(Pi[q],  C10[k], Xi);
                Xi = fmaf(Mr[q], -S10[k], Xi);
            }
            outp[m + 10 * j] = sclog(fmaf(Xr, Xr, Xi * Xi));
        }
        if (m == 0) {   // f = 50: Z real, X[50] = or - P1 + P2 - P3 + P4
            float Xr = orr - P[1] + P[2] - P[3] + P[4];
            outp[50] = sclog(Xr * Xr);
        }
    }
    __syncwarp();

    // ---- stage 3: write-out (fast path: one segment per warp-triple) ----
    {
        const int b0 = gbase & 255;
        if (b0 <= 253 && gbase + 2 < TOT_T) {
            const int seg = gbase >> 8;
            float* __restrict__ dst = &g_L[t][seg][b0 * NFREQ];
            const float* __restrict__ srcp = psd_s[base_inst];
            #pragma unroll
            for (int i = 0; i < 4; ++i)
                dst[lane + i * 32] = srcp[lane + i * 32];
            if (lane + 128 < 3 * NFREQ)
                dst[lane + 128] = srcp[lane + 128];
        } else {
            for (int i = lane; i < 3 * NFREQ; i += 32) {
                int k = i / NFREQ, f = i - k * NFREQ;
                int g = gbase + k;
                if (g >= TOT_T) break;
                int seg = g >> 8, b = g & 255;
                g_L[t][seg][b * NFREQ + f] = psd_s[base_inst + k][f];
            }
        }
    }
}

// ---------------------------------------------------------------------------
// Kernel B: fused per-segment normalize + column sums + sum of squares.
__global__ __launch_bounds__(256) void norm_kernel() {
    const int blk = blockIdx.x;
    const int t   = blk / NORMBLKS;
    const int c   = blk % NORMBLKS;
    const int r   = threadIdx.x;

    float csum[NFREQ];
    #pragma unroll
    for (int j = 0; j < NFREQ; ++j) csum[j] = 0.0f;
    float ssq = 0.0f;

    #pragma unroll
    for (int k = 0; k < NSPB; ++k) {
        const int s = c * NSPB + k;
        const float* __restrict__ L = g_L[t][s];
        float v[NFREQ];
        float mn = FLT_MAX, mx = -FLT_MAX;
        #pragma unroll
        for (int j = 0; j < NFREQ; ++j) {
            float x = L[j * 256 + r];
            v[j] = x;
            mn = fminf(mn, x);
            mx = fmaxf(mx, x);
        }
        const float inv = 1.0f / (mx - mn);
        #pragma unroll
        for (int j = 0; j < NFREQ; ++j) {
            float x = (v[j] - mn) * inv;
            csum[j] += x;
            ssq = fmaf(x, x, ssq);
        }
    }

    #pragma unroll
    for (int j = 0; j < NFREQ; ++j)
        atomicAdd(&g_colsum[t][j * 256 + r], csum[j]);

    __shared__ float red[256];
    red[r] = ssq;
    __syncthreads();
    for (int off = 128; off > 0; off >>= 1) {
        if (r < off) red[r] += red[r + off];
        __syncthreads();
    }
    if (r == 0) atomicAdd(&g_saTot[t], (double)red[0]);
}

// ---------------------------------------------------------------------------
// Kernel C: dot products over column sums + final combine in the last block.
__global__ __launch_bounds__(256) void dot_final_kernel(float* __restrict__ out) {
    const int i = blockIdx.x * 256 + threadIdx.x;
    double SF = (double)g_colsum[0][i];
    double SR = (double)g_colsum[1][i];
    double d = SF * SR, q = SF * SF;

    __shared__ double rd[256], rq[256];
    rd[threadIdx.x] = d; rq[threadIdx.x] = q;
    __syncthreads();
    for (int off = 128; off > 0; off >>= 1) {
        if (threadIdx.x < off) {
            rd[threadIdx.x] += rd[threadIdx.x + off];
            rq[threadIdx.x] += rq[threadIdx.x + off];
        }
        __syncthreads();
    }
    __shared__ bool last;
    if (threadIdx.x == 0) {
        atomicAdd(&g_acc[0], rd[0]);
        atomicAdd(&g_acc[1], rq[0]);
        __threadfence();
        unsigned int prev = atomicAdd(&g_done, 1u);
        last = (prev == (unsigned int)(COLS / 256 - 1));
    }
    __syncthreads();
    if (last && threadIdx.x == 0) {
        const double SA = g_saTot[0], SB = g_saTot[1];
        const double n  = (double)COLS;
        const double ns = (double)NSEG;
        const double m  = ns * (ns - 1.0) * 0.5;
        out[0] = (float)((SA / ns + SB / ns - 2.0 * g_acc[0] / (ns * ns)) / n);
        out[1] = (float)((ns * SA - g_acc[1]) / (n * m));
    }
}

// ---------------------------------------------------------------------------
extern "C" void kernel_launch(void* const* d_in, const int* in_sizes, int n_in,
                              void* d_out, int out_size) {
    const float* fake  = (const float*)d_in[0];
    const float* real_ = (const float*)d_in[1];
    float* out = (float*)d_out;

    dim3 pg(PSDBLKX, T2);
    psd_kernel<<<pg, PSDTHR>>>(fake, real_);
    norm_kernel<<<T2 * NORMBLKS, 256>>>();
    dot_final_kernel<<<COLS / 256, 256>>>(out);
}

// round 16
// speedup vs baseline: 1.4448x; 1.4448x over previous
#include <cuda_runtime.h>
#include <math.h>
#include <float.h>

#define T2       2
#define BATCH    256
#define NSAMP    80000
#define NPERSEG  100
#define NFREQ    51
#define NSEG     800
#define COLS     (BATCH * NFREQ)         // 13056 = 51*256
#define NSPB     2
#define NORMBLKS (NSEG / NSPB)           // 400
#define IPB      42                      // instances per psd block (14 warps x 3)
#define PSDTHR   448
#define XS_W     108                     // padded xs row stride (words); 108%32=12
#define TOT_T    (NSEG * BATCH)          // 204800 per tensor
#define PSDBLKX  ((TOT_T + IPB - 1) / IPB)  // 4877

#define TWO_PI 6.28318530717958647692f

__device__ constexpr float C10[10] = {
     1.0f,  0.80901699437494745f,  0.30901699437494745f, -0.30901699437494745f,
    -0.80901699437494745f, -1.0f, -0.80901699437494745f, -0.30901699437494745f,
     0.30901699437494745f,  0.80901699437494745f };
__device__ constexpr float S10[10] = {
     0.0f,  0.58778525229247314f,  0.95105651629515353f,  0.95105651629515353f,
     0.58778525229247314f,  0.0f, -0.58778525229247314f, -0.95105651629515353f,
    -0.95105651629515353f, -0.58778525229247314f };

// Scratch: signed-clamp-log PSD (unnormalized). 83.6 MB.
__device__ float  g_L[T2][NSEG][COLS];
__device__ float  g_colsum[T2][COLS];
__device__ double g_saTot[T2];
__device__ double g_acc[2];      // [0]=sum SF*SR, [1]=sum SF*SF
__device__ unsigned int g_done;  // dot-block completion counter

__device__ __forceinline__ float sclog(float p) {
    float lx = __logf(p);
    float s  = (lx > 0.0f) ? 1.0f : ((lx < 0.0f) ? -1.0f : 0.0f);
    return s * fmaxf(fabsf(lx), 1e-6f);
}

__device__ __forceinline__ float2 cmul(float2 a, float2 b) {
    return make_float2(fmaf(a.x, b.x, -a.y * b.y), fmaf(a.x, b.y, a.y * b.x));
}

// ---------------------------------------------------------------------------
// Kernel A: Welch -> 10x10 CT rDFT(100), real/conjugate folded.
// Grid (PSDBLKX, 2); blockIdx.y = tensor. Warp = 3 instances x 10 lanes.
// Stage-2 twiddles from register recurrence. min-4-blocks forces regs <= 36.
__global__ __launch_bounds__(PSDTHR, 4) void psd_kernel(const float* __restrict__ fake,
                                                        const float* __restrict__ real_) {
    __shared__ __align__(16) float wnd[NPERSEG];
    __shared__ float2 tws[NPERSEG];          // e^{-2 pi i k/100}
    __shared__ __align__(16) float xs[IPB][XS_W];
    __shared__ float2 Ysh[IPB][10][6];
    __shared__ float  psd_s[IPB][NFREQ];

    const int tid = threadIdx.x;

    // Fold in accumulator zeroing (replaces zero_kernel).
    if (blockIdx.y == 0) {
        int gid = blockIdx.x * PSDTHR + tid;
        if (gid < T2 * COLS) ((float*)g_colsum)[gid] = 0.0f;
        if (blockIdx.x == 0) {
            if (tid < T2) g_saTot[tid] = 0.0;
            if (tid >= 2 && tid < 4) g_acc[tid - 2] = 0.0;
            if (tid == 4) g_done = 0u;
        }
    }

    if (tid < NPERSEG) {
        float s, c;
        sincosf(TWO_PI * 0.01f * (float)tid, &s, &c);
        tws[tid] = make_float2(c, -s);
        wnd[tid] = 1.0f - c;                 // hann(periodic)*2
    }
    __syncthreads();

    const int t = blockIdx.y;
    const float* __restrict__ base = (t == 0) ? fake : real_;

    const int warp = tid >> 5, lane = tid & 31;
    const int base_inst = warp * 3;
    const int gbase = blockIdx.x * IPB + base_inst;   // per-tensor instance id

    // ---- stage 0: vectorized load + clamp + window into smem (float4) ----
    #pragma unroll
    for (int k = 0; k < 3; ++k) {
        int g = gbase + k;
        if (g >= TOT_T) break;
        int seg = g >> 8, b = g & 255;
        const float4* __restrict__ src4 =
            (const float4*)(base + (size_t)b * NSAMP + seg * NPERSEG);
        if (lane < 25) {
            float4 v = src4[lane];
            float4 w = ((const float4*)wnd)[lane];
            float4 o;
            o.x = fmaxf(v.x, 1e-6f) * w.x;
            o.y = fmaxf(v.y, 1e-6f) * w.y;
            o.z = fmaxf(v.z, 1e-6f) * w.z;
            o.w = fmaxf(v.w, 1e-6f) * w.w;
            ((float4*)xs[base_inst + k])[lane] = o;
        }
    }
    __syncwarp();

    const int  ik   = lane / 10;             // 0..2
    const int  role = lane - ik * 10;        // 0..9 (q in stage1, m in stage2)
    const int  inst = base_inst + ik;
    const bool act  = (lane < 30) && (gbase + ik < TOT_T);

    // ---- stage 1: Y[q][r] = sum_a x[10a+q] w10^{ra}, r=0..5, real-folded ----
    if (act) {
        float x[10];
        #pragma unroll
        for (int a = 0; a < 10; ++a) x[a] = xs[inst][a * 10 + role];
        float s1 = x[1] + x[9], d1 = x[1] - x[9];
        float s2 = x[2] + x[8], d2 = x[2] - x[8];
        float s3 = x[3] + x[7], d3 = x[3] - x[7];
        float s4 = x[4] + x[6], d4 = x[4] - x[6];
        float ex = x[0] + x[5], ox = x[0] - x[5];
        float sv[5] = {0.0f, s1, s2, s3, s4};
        float dv[5] = {0.0f, d1, d2, d3, d4};

        Ysh[inst][role][0] = make_float2(ex + s1 + s2 + s3 + s4, 0.0f);
        Ysh[inst][role][5] = make_float2(ox - s1 + s2 - s3 + s4, 0.0f);
        #pragma unroll
        for (int r = 1; r < 5; ++r) {
            float re = (r & 1) ? ox : ex;
            float im = 0.0f;
            #pragma unroll
            for (int a = 1; a < 5; ++a) {
                const int k = (r * a) % 10;
                re = fmaf(sv[a],  C10[k], re);
                im = fmaf(dv[a], -S10[k], im);
            }
            Ysh[inst][role][r] = make_float2(re, im);
        }
    }
    __syncwarp();

    // ---- stage 2: Z[q] = e1^q * Y~[q]; DFT-10 over j with q-folding -------
    if (act) {
        const int   m  = role;
        const int   c  = (m <= 5) ? m : 10 - m;
        const float cj = (m <= 5) ? 1.0f : -1.0f;

        const float2 e1 = tws[m];            // single LDS.64
        const float2 e2 = cmul(e1, e1);

        float Zr[10], Zi[10];
        {
            float2 y = Ysh[inst][0][c];
            Zr[0] = y.x;
            Zi[0] = y.y * cj;
        }
        {   // odd chain: q = 1,3,5,7,9 stepping by e2
            float2 e = e1;
            #pragma unroll
            for (int q = 1; q <= 9; q += 2) {
                float2 y = Ysh[inst][q][c];
                float  yi = y.y * cj;
                Zr[q] = fmaf(e.x, y.x, -e.y * yi);
                Zi[q] = fmaf(e.x, yi,   e.y * y.x);
                if (q < 9) e = cmul(e, e2);
            }
        }
        {   // even chain: q = 2,4,6,8 stepping by e2
            float2 e = e2;
            #pragma unroll
            for (int q = 2; q <= 8; q += 2) {
                float2 y = Ysh[inst][q][c];
                float  yi = y.y * cj;
                Zr[q] = fmaf(e.x, y.x, -e.y * yi);
                Zi[q] = fmaf(e.x, yi,   e.y * y.x);
                if (q < 8) e = cmul(e, e2);
            }
        }

        float P[5], Mr[5], Pi[5], Mi[5];
        #pragma unroll
        for (int q = 1; q < 5; ++q) {
            P [q] = Zr[q] + Zr[10 - q];
            Mr[q] = Zr[q] - Zr[10 - q];
            Pi[q] = Zi[q] + Zi[10 - q];
            Mi[q] = Zi[q] - Zi[10 - q];
        }
        const float er = Zr[0] + Zr[5], orr = Zr[0] - Zr[5];
        const float ei = Zi[0] + Zi[5], oi  = Zi[0] - Zi[5];

        float* outp = psd_s[inst];
        {
            float Xr = er + P[1] + P[2] + P[3] + P[4];
            float Xi = ei + Pi[1] + Pi[2] + Pi[3] + Pi[4];
            outp[m] = sclog(fmaf(Xr, Xr, Xi * Xi));
        }
        #pragma unroll
        for (int j = 1; j < 5; ++j) {
            float Xr = (j & 1) ? orr : er;
            float Xi = (j & 1) ? oi  : ei;
            #pragma unroll
            for (int q = 1; q < 5; ++q) {
                const int k = (j * q) % 10;
                Xr = fmaf(P [q],  C10[k], Xr);
                Xr = fmaf(Mi[q],  S10[k], Xr);
                Xi = fmaf(Pi[q],  C10[k], Xi);
                Xi = fmaf(Mr[q], -S10[k], Xi);
            }
            outp[m + 10 * j] = sclog(fmaf(Xr, Xr, Xi * Xi));
        }
        if (m == 0) {   // f = 50: Z real, X[50] = or - P1 + P2 - P3 + P4
            float Xr = orr - P[1] + P[2] - P[3] + P[4];
            outp[50] = sclog(Xr * Xr);
        }
    }
    __syncwarp();

    // ---- stage 3: write-out (fast path: one segment per warp-triple) ----
    {
        const int b0 = gbase & 255;
        if (b0 <= 253 && gbase + 2 < TOT_T) {
            const int seg = gbase >> 8;
            float* __restrict__ dst = &g_L[t][seg][b0 * NFREQ];
            const float* __restrict__ srcp = psd_s[base_inst];
            #pragma unroll
            for (int i = 0; i < 4; ++i)
                dst[lane + i * 32] = srcp[lane + i * 32];
            if (lane + 128 < 3 * NFREQ)
                dst[lane + 128] = srcp[lane + 128];
        } else {
            for (int i = lane; i < 3 * NFREQ; i += 32) {
                int k = i / NFREQ, f = i - k * NFREQ;
                int g = gbase + k;
                if (g >= TOT_T) break;
                int seg = g >> 8, b = g & 255;
                g_L[t][seg][b * NFREQ + f] = psd_s[base_inst + k][f];
            }
        }
    }
}

// ---------------------------------------------------------------------------
// Kernel B: fused per-segment normalize + column sums + sum of squares.
__global__ __launch_bounds__(256) void norm_kernel() {
    const int blk = blockIdx.x;
    const int t   = blk / NORMBLKS;
    const int c   = blk % NORMBLKS;
    const int r   = threadIdx.x;

    float csum[NFREQ];
    #pragma unroll
    for (int j = 0; j < NFREQ; ++j) csum[j] = 0.0f;
    float ssq = 0.0f;

    #pragma unroll
    for (int k = 0; k < NSPB; ++k) {
        const int s = c * NSPB + k;
        const float* __restrict__ L = g_L[t][s];
        float v[NFREQ];
        float mn = FLT_MAX, mx = -FLT_MAX;
        #pragma unroll
        for (int j = 0; j < NFREQ; ++j) {
            float x = L[j * 256 + r];
            v[j] = x;
            mn = fminf(mn, x);
            mx = fmaxf(mx, x);
        }
        const float inv = 1.0f / (mx - mn);
        #pragma unroll
        for (int j = 0; j < NFREQ; ++j) {
            float x = (v[j] - mn) * inv;
            csum[j] += x;
            ssq = fmaf(x, x, ssq);
        }
    }

    #pragma unroll
    for (int j = 0; j < NFREQ; ++j)
        atomicAdd(&g_colsum[t][j * 256 + r], csum[j]);

    __shared__ float red[256];
    red[r] = ssq;
    __syncthreads();
    for (int off = 128; off > 0; off >>= 1) {
        if (r < off) red[r] += red[r + off];
        __syncthreads();
    }
    if (r == 0) atomicAdd(&g_saTot[t], (double)red[0]);
}

// ---------------------------------------------------------------------------
// Kernel C: dot products over column sums + final combine in the last block.
__global__ __launch_bounds__(256) void dot_final_kernel(float* __restrict__ out) {
    const int i = blockIdx.x * 256 + threadIdx.x;
    double SF = (double)g_colsum[0][i];
    double SR = (double)g_colsum[1][i];
    double d = SF * SR, q = SF * SF;

    __shared__ double rd[256], rq[256];
    rd[threadIdx.x] = d; rq[threadIdx.x] = q;
    __syncthreads();
    for (int off = 128; off > 0; off >>= 1) {
        if (threadIdx.x < off) {
            rd[threadIdx.x] += rd[threadIdx.x + off];
            rq[threadIdx.x] += rq[threadIdx.x + off];
        }
        __syncthreads();
    }
    __shared__ bool last;
    if (threadIdx.x == 0) {
        atomicAdd(&g_acc[0], rd[0]);
        atomicAdd(&g_acc[1], rq[0]);
        __threadfence();
        unsigned int prev = atomicAdd(&g_done, 1u);
        last = (prev == (unsigned int)(COLS / 256 - 1));
    }
    __syncthreads();
    if (last && threadIdx.x == 0) {
        const double SA = g_saTot[0], SB = g_saTot[1];
        const double n  = (double)COLS;
        const double ns = (double)NSEG;
        const double m  = ns * (ns - 1.0) * 0.5;
        out[0] = (float)((SA / ns + SB / ns - 2.0 * g_acc[0] / (ns * ns)) / n);
        out[1] = (float)((ns * SA - g_acc[1]) / (n * m));
    }
}

// ---------------------------------------------------------------------------
extern "C" void kernel_launch(void* const* d_in, const int* in_sizes, int n_in,
                              void* d_out, int out_size) {
    const float* fake  = (const float*)d_in[0];
    const float* real_ = (const float*)d_in[1];
    float* out = (float*)d_out;

    dim3 pg(PSDBLKX, T2);
    psd_kernel<<<pg, PSDTHR>>>(fake, real_);
    norm_kernel<<<T2 * NORMBLKS, 256>>>();
    dot_final_kernel<<<COLS / 256, 256>>>(out);
}